// round 5
// baseline (speedup 1.0000x reference)
#include <cuda_runtime.h>
#include <cstdint>

#define NFINE   1000000
#define FE      9
#define KDIM    288
#define NF      64
#define BLOCK_M 256
#define THREADS 512              // 16 warps: (wid&7)=m-tile(m32), (wid>>3)=n-half(n32)
#define WSTRIDE 72               // B row stride (floats): conflict-free B LDS
#define ASTRIDE 36               // A row stride (floats): bank=(4r+c)%32, conflict-free

// smem layout (u32 units)
#define WS_U32   (KDIM * WSTRIDE)            // 20736
#define A_OFF    WS_U32                      // 3 slab buffers
#define A_U32    (BLOCK_M * ASTRIDE)         // 9216 per buffer (36864 B)
#define IDX_OFF  (A_OFF + 3 * A_U32)         // 48384
#define IDX_U32  (BLOCK_M * FE)              // 2304 per idx buffer
#define MBAR_U32 (IDX_OFF + 2 * IDX_U32)     // 52992 (8B-aligned: even)
#define SMEM_U32 (MBAR_U32 + 16)
#define SMEM_BYTES (SMEM_U32 * 4)            // 212032 B -> 1 CTA/SM

__device__ __forceinline__ void mbar_init(uint32_t a, uint32_t c) {
    asm volatile("mbarrier.init.shared.b64 [%0], %1;" :: "r"(a), "r"(c) : "memory");
}
__device__ __forceinline__ void mbar_wait(uint32_t a, uint32_t ph) {
    uint32_t done;
    asm volatile("{\n\t.reg .pred P;\n\t"
                 "mbarrier.try_wait.parity.acquire.cta.shared::cta.b64 P, [%1], %2;\n\t"
                 "selp.b32 %0, 1, 0, P;\n\t}" : "=r"(done) : "r"(a), "r"(ph) : "memory");
    if (!done) {
        asm volatile("{\n\t.reg .pred P;\n\t"
                     "LW_%=:\n\t"
                     "mbarrier.try_wait.parity.acquire.cta.shared::cta.b64 P, [%0], %1, 0x989680;\n\t"
                     "@P bra.uni LD_%=;\n\t"
                     "bra.uni LW_%=;\n\t"
                     "LD_%=:\n\t}" :: "r"(a), "r"(ph) : "memory");
    }
}
__device__ __forceinline__ void arrive_tx(uint32_t mbar, uint32_t bytes) {
    asm volatile("mbarrier.arrive.expect_tx.shared.b64 _, [%0], %1;"
                 :: "r"(mbar), "r"(bytes) : "memory");
}
__device__ __forceinline__ void bulk_g2s(uint32_t dst, const void* src,
                                         uint32_t bytes, uint32_t mbar) {
    asm volatile("cp.async.bulk.shared::cluster.global.mbarrier::complete_tx::bytes "
                 "[%0], [%1], %2, [%3];"
                 :: "r"(dst), "l"(src), "r"(bytes), "r"(mbar) : "memory");
}

// Gather one neighbor slab: 256 rows x 128B via one bulk op per row (threads 0-255).
// mbar armed with 256 arrivals + 32768 tx bytes per phase.
__device__ __forceinline__ void gather_slab(const float* __restrict__ coarse,
                                            const int* __restrict__ sidx, int j,
                                            uint32_t abuf, uint32_t mbar)
{
    if (threadIdx.x < 256) {
        int idx = sidx[threadIdx.x * FE + j];          // stride 9: conflict-free
        arrive_tx(mbar, 128);
        bulk_g2s(abuf + threadIdx.x * (ASTRIDE * 4),
                 (const char*)coarse + ((size_t)(unsigned)idx << 7), 128, mbar);
    }
}

// Stage neighbor indices for one tile: single bulk op (tail: in-bounds bytes only;
// stale tail rows keep older valid indices -> safe, and their outputs are masked).
__device__ __forceinline__ void stage_idx(const int* __restrict__ nbr, int tile,
                                          uint32_t dst, uint32_t mbar)
{
    if (threadIdx.x == 0) {
        size_t base = (size_t)tile * (BLOCK_M * FE);
        size_t remain = (size_t)NFINE * FE - base;
        uint32_t bytes = remain >= BLOCK_M * FE ? BLOCK_M * FE * 4 : (uint32_t)remain * 4;
        arrive_tx(mbar, bytes);
        bulk_g2s(dst, nbr + base, bytes, mbar);
    }
}

__global__ void __launch_bounds__(THREADS, 1)
finefy_tf32_kernel(const float* __restrict__ coarse,
                   const int*   __restrict__ nbr,
                   const float* __restrict__ weight,
                   float*       __restrict__ out,
                   int numTiles)
{
    extern __shared__ uint32_t sm_[];
    uint32_t* ws = sm_;
    const uint32_t sb = (uint32_t)__cvta_generic_to_shared(sm_);
    const uint32_t mb = sb + MBAR_U32 * 4;      // mbarA[i]=mb+8i, mbarI[i]=mb+24+8i
    const uint32_t abase = sb + A_OFF * 4;

    const int tid  = threadIdx.x;
    const int lane = tid & 31;
    const int wid  = tid >> 5;
    const int qr   = lane >> 2;
    const int qc   = lane & 3;
    const int mw   = wid & 7;
    const int nh   = wid >> 3;

    // Weight -> tf32 into padded smem, once.
    for (int i = tid; i < KDIM * NF; i += THREADS) {
        int k = i >> 6, n = i & 63;
        uint32_t t;
        asm("cvt.rna.tf32.f32 %0, %1;" : "=r"(t) : "f"(weight[i]));
        ws[k * WSTRIDE + n] = t;
    }
    if (tid == 0) {
        mbar_init(mb,      256); mbar_init(mb + 8,  256); mbar_init(mb + 16, 256);
        mbar_init(mb + 24, 1);   mbar_init(mb + 32, 1);
    }
    __syncthreads();   // ws + mbar init visible

    const int step = gridDim.x;
    int tile = blockIdx.x;
    int ibuf = 0;
    int phA0 = 0, phA1 = 0, phA2 = 0, phI0 = 0, phI1 = 0;

    if (tile < numTiles) {
        stage_idx(nbr, tile, sb + IDX_OFF * 4, mb + 24);
        if (tid < 256) { mbar_wait(mb + 24, phI0); }
        phI0 ^= 1;   // tracked uniformly; only tid<256 ever wait mbarI
        const int* sidx0 = (const int*)(sm_ + IDX_OFF);
        gather_slab(coarse, sidx0, 0, abase,               mb);
        gather_slab(coarse, sidx0, 1, abase + A_U32 * 4,   mb + 8);
    }

    for (; tile < numTiles; tile += step) {
        const int* sidx  = (const int*)(sm_ + IDX_OFF + ibuf * IDX_U32);
        const int* nsidx = (const int*)(sm_ + IDX_OFF + (ibuf ^ 1) * IDX_U32);
        const bool has_next = (tile + step) < numTiles;

        float acc[8][4];
        #pragma unroll
        for (int i = 0; i < 8; ++i) {
            acc[i][0] = 0.f; acc[i][1] = 0.f; acc[i][2] = 0.f; acc[i][3] = 0.f;
        }

        #pragma unroll
        for (int j = 0; j < FE; ++j) {
            const int b = j % 3;

            // Produce: slab j+2 (same tile) or next tile's slab 0/1.
            if (j <= FE - 3) {
                const int nb = (j + 2) % 3;
                gather_slab(coarse, sidx, j + 2, abase + nb * (A_U32 * 4), mb + nb * 8);
            } else if (has_next) {
                if (j == FE - 2) {
                    if (tid < 256) { mbar_wait(mb + 24 + (ibuf ^ 1) * 8,
                                               (ibuf ^ 1) ? phI1 : phI0); }
                    if (ibuf ^ 1) phI1 ^= 1; else phI0 ^= 1;
                    gather_slab(coarse, nsidx, 0, abase, mb);
                } else { // j == FE-1
                    gather_slab(coarse, nsidx, 1, abase + A_U32 * 4, mb + 8);
                }
            }
            if (j == 4 && has_next)
                stage_idx(nbr, tile + step,
                          sb + (IDX_OFF + (ibuf ^ 1) * IDX_U32) * 4,
                          mb + 24 + (ibuf ^ 1) * 8);

            // Consume slab j.
            mbar_wait(mb + b * 8, b == 0 ? phA0 : (b == 1 ? phA1 : phA2));
            if (b == 0) phA0 ^= 1; else if (b == 1) phA1 ^= 1; else phA2 ^= 1;

            const uint32_t* ar = sm_ + A_OFF + b * A_U32 + (mw * 32 + qr) * ASTRIDE + qc;

            #pragma unroll
            for (int kk = 0; kk < 4; ++kk) {
                const int c = kk * 8;
                uint32_t a0 = ar[c];
                uint32_t a2 = ar[c + 4];
                uint32_t a1 = ar[c + 8  * ASTRIDE];
                uint32_t a3 = ar[c + 8  * ASTRIDE + 4];
                uint32_t a4 = ar[c + 16 * ASTRIDE];
                uint32_t a6 = ar[c + 16 * ASTRIDE + 4];
                uint32_t a5 = ar[c + 24 * ASTRIDE];
                uint32_t a7 = ar[c + 24 * ASTRIDE + 4];

                const uint32_t* wrow = ws + (j * 32 + kk * 8 + qc) * WSTRIDE + nh * 32 + qr;

                #pragma unroll
                for (int t = 0; t < 4; ++t) {
                    uint32_t b0 = wrow[t * 8];
                    uint32_t b1 = wrow[t * 8 + 4 * WSTRIDE];
                    asm volatile(
                        "mma.sync.aligned.m16n8k8.row.col.f32.tf32.tf32.f32 "
                        "{%0,%1,%2,%3}, {%4,%5,%6,%7}, {%8,%9}, {%0,%1,%2,%3};"
                        : "+f"(acc[2*t][0]), "+f"(acc[2*t][1]),
                          "+f"(acc[2*t][2]), "+f"(acc[2*t][3])
                        : "r"(a0), "r"(a1), "r"(a2), "r"(a3), "r"(b0), "r"(b1));
                    asm volatile(
                        "mma.sync.aligned.m16n8k8.row.col.f32.tf32.tf32.f32 "
                        "{%0,%1,%2,%3}, {%4,%5,%6,%7}, {%8,%9}, {%0,%1,%2,%3};"
                        : "+f"(acc[2*t+1][0]), "+f"(acc[2*t+1][1]),
                          "+f"(acc[2*t+1][2]), "+f"(acc[2*t+1][3])
                        : "r"(a4), "r"(a5), "r"(a6), "r"(a7), "r"(b0), "r"(b1));
                }
            }
            __syncthreads();   // all warps done with slab j before its buffer is re-armed
        }

        // Epilogue (next tile's slab 0/1 bulk copies land underneath).
        const int rowbase = tile * BLOCK_M;
        #pragma unroll
        for (int s = 0; s < 2; ++s) {
            #pragma unroll
            for (int h = 0; h < 2; ++h) {
                int r = rowbase + mw * 32 + s * 16 + h * 8 + qr;
                if (r < NFINE) {
                    float2* po = (float2*)(out + (size_t)r * NF + nh * 32 + qc * 2);
                    #pragma unroll
                    for (int t = 0; t < 4; ++t)
                        __stcs(po + t * 4,
                               make_float2(acc[2*t + s][2*h], acc[2*t + s][2*h + 1]));
                }
            }
        }
        ibuf ^= 1;
    }
}

extern "C" void kernel_launch(void* const* d_in, const int* in_sizes, int n_in,
                              void* d_out, int out_size)
{
    const float* coarse = (const float*)d_in[0];   // [250000, 32] f32
    const int*   nbr    = (const int*)  d_in[1];   // [1000000, 9] i32
    const float* weight = (const float*)d_in[2];   // [288, 64] f32
    float*       out    = (float*)d_out;           // [1000000, 64] f32

    cudaFuncSetAttribute(finefy_tf32_kernel,
                         cudaFuncAttributeMaxDynamicSharedMemorySize, SMEM_BYTES);

    int nsm = 148;
    cudaDeviceGetAttribute(&nsm, cudaDevAttrMultiProcessorCount, 0);

    const int numTiles = (NFINE + BLOCK_M - 1) / BLOCK_M;   // 3907
    finefy_tf32_kernel<<<nsm, THREADS, SMEM_BYTES>>>(coarse, nbr, weight, out, numTiles);
}

// round 6
// speedup vs baseline: 1.5780x; 1.5780x over previous
#include <cuda_runtime.h>
#include <cuda_fp16.h>
#include <cstdint>

#define NFINE   1000000
#define NCOARSE 250000
#define FE      9
#define NF      64
#define BLOCK_M 256
#define THREADS 512              // 16 warps: (wid&7)=m-tile(m32), (wid>>3)=n-half(n32)
#define WSTRIDE 72               // B half2-row stride (u32 words): bank=(8qc+qr)%32 bijective
#define ASTRIDE 20               // A row stride (u32 words): 64B data + 16B pad,
                                 // bank=(20qr+qc)%32 bijective -> conflict-free

// smem layout (u32 units)
#define WS_U32   (144 * WSTRIDE)           // 10368 (288 halves = 144 half2 rows)
#define A_OFF    WS_U32
#define A_U32    (BLOCK_M * ASTRIDE)       // 5120 per slab buffer
#define IDX_OFF  (A_OFF + 2 * A_U32)       // 20608
#define IDX_U32  (BLOCK_M * FE)            // 2304 per idx buffer
#define SMEM_U32 (IDX_OFF + 2 * IDX_U32)   // 25216
#define SMEM_BYTES (SMEM_U32 * 4)          // 100864 B

// fp16 copy of coarse values (filled by conv_coarse pre-pass each launch)
__device__ __half g_ch[NCOARSE * 32];      // 16 MB

__global__ void __launch_bounds__(256)
conv_coarse(const float4* __restrict__ src)
{
    uint2* dst = (uint2*)g_ch;
    const int n4 = NCOARSE * 8;            // 2,000,000 float4s
    for (int i = blockIdx.x * blockDim.x + threadIdx.x; i < n4;
         i += gridDim.x * blockDim.x) {
        float4 v = src[i];
        __half2 h0 = __floats2half2_rn(v.x, v.y);
        __half2 h1 = __floats2half2_rn(v.z, v.w);
        dst[i] = make_uint2(*(uint32_t*)&h0, *(uint32_t*)&h1);
    }
}

__device__ __forceinline__ void cp_commit() { asm volatile("cp.async.commit_group;"); }
template<int N> __device__ __forceinline__ void cp_wait() {
    asm volatile("cp.async.wait_group %0;" :: "n"(N));
}

// Gather one neighbor slab j: 256 rows x 64B, 2 cp.async(16B) per thread.
__device__ __forceinline__ void gather_slab(const int* __restrict__ sidx, int j,
                                            uint32_t abuf)
{
    #pragma unroll
    for (int i = 0; i < 2; ++i) {
        int o   = i * THREADS + threadIdx.x;   // 0..1023
        int r   = o >> 2;
        int seg = o & 3;
        int idx = sidx[r * FE + j];
        const char* src = (const char*)g_ch + ((size_t)(unsigned)idx << 6) + (seg << 4);
        uint32_t dst = abuf + (uint32_t)r * (ASTRIDE * 4) + (uint32_t)(seg << 4);
        asm volatile("cp.async.cg.shared.global [%0], [%1], 16;" :: "r"(dst), "l"(src));
    }
}

// Stage 256x9 neighbor indices for one tile (tail: clamp, stale rows stay valid).
__device__ __forceinline__ void stage_idx(const int* __restrict__ nbr, int tile,
                                          uint32_t dst)
{
    const size_t base = (size_t)tile * (BLOCK_M * FE);
    if (base + BLOCK_M * FE <= (size_t)NFINE * FE) {
        #pragma unroll
        for (int c = threadIdx.x; c < BLOCK_M * FE / 4; c += THREADS)
            asm volatile("cp.async.ca.shared.global [%0], [%1], 16;"
                         :: "r"(dst + c * 16), "l"(nbr + base + c * 4));
    } else {
        const size_t gmax = (size_t)NFINE * FE - 1;
        for (int i = threadIdx.x; i < BLOCK_M * FE; i += THREADS) {
            size_t g = base + i; if (g > gmax) g = gmax;
            asm volatile("cp.async.ca.shared.global [%0], [%1], 4;"
                         :: "r"(dst + i * 4), "l"(nbr + g));
        }
    }
}

__global__ void __launch_bounds__(THREADS, 1)
finefy_fp16_kernel(const int*   __restrict__ nbr,
                   const float* __restrict__ weight,
                   float*       __restrict__ out,
                   int numTiles)
{
    extern __shared__ uint32_t sm_[];
    uint32_t* ws = sm_;
    const uint32_t sb = (uint32_t)__cvta_generic_to_shared(sm_);

    const int tid  = threadIdx.x;
    const int lane = tid & 31;
    const int wid  = tid >> 5;
    const int qr   = lane >> 2;      // 0..7
    const int qc   = lane & 3;       // 0..3
    const int mw   = wid & 7;        // m-tile (rows mw*32..+31)
    const int nh   = wid >> 3;       // n-half (cols nh*32..+31)

    // Weight -> fp16, packed as half2 along K: B half index = (r*WSTRIDE+n)*2 + (k&1)
    for (int i = tid; i < 288 * NF; i += THREADS) {
        int k = i >> 6, n = i & 63;
        ((__half*)ws)[((k >> 1) * WSTRIDE + n) * 2 + (k & 1)] = __float2half_rn(weight[i]);
    }

    const int step = gridDim.x;
    int tile = blockIdx.x;
    int ibuf = 0;   // idx buffer for current tile
    int sbuf = 0;   // slab buffer about to be computed

    if (tile < numTiles) {
        stage_idx(nbr, tile, sb + IDX_OFF * 4);
        cp_commit(); cp_wait<0>(); __syncthreads();
        gather_slab((const int*)(sm_ + IDX_OFF), 0, sb + A_OFF * 4);
        cp_commit();
    }

    for (; tile < numTiles; tile += step) {
        const int* sidx = (const int*)(sm_ + IDX_OFF + ibuf * IDX_U32);

        float acc[8][4];
        #pragma unroll
        for (int i = 0; i < 8; ++i) {
            acc[i][0] = 0.f; acc[i][1] = 0.f; acc[i][2] = 0.f; acc[i][3] = 0.f;
        }

        for (int j = 0; j < FE; ++j) {
            if (j < FE - 1) {
                gather_slab(sidx, j + 1, sb + (A_OFF + (sbuf ^ 1) * A_U32) * 4);
                if (j == FE - 2 && tile + step < numTiles)
                    stage_idx(nbr, tile + step, sb + (IDX_OFF + (ibuf ^ 1) * IDX_U32) * 4);
                cp_commit();
                cp_wait<1>();            // slab j landed; j+1 in flight
            } else {
                cp_wait<0>();            // last slab (+ next idx) landed
            }
            __syncthreads();

            const uint32_t* ar = sm_ + A_OFF + sbuf * A_U32 + (mw * 32 + qr) * ASTRIDE + qc;

            #pragma unroll
            for (int kk = 0; kk < 2; ++kk) {     // two k16 steps cover 32 dims
                const int c = kk * 8;
                uint32_t a0 = ar[c];
                uint32_t a2 = ar[c + 4];
                uint32_t a1 = ar[c     + 8  * ASTRIDE];
                uint32_t a3 = ar[c + 4 + 8  * ASTRIDE];
                uint32_t a4 = ar[c     + 16 * ASTRIDE];
                uint32_t a6 = ar[c + 4 + 16 * ASTRIDE];
                uint32_t a5 = ar[c     + 24 * ASTRIDE];
                uint32_t a7 = ar[c + 4 + 24 * ASTRIDE];

                const uint32_t* wrow = ws + (j * 16 + kk * 8 + qc) * WSTRIDE + nh * 32 + qr;

                #pragma unroll
                for (int t = 0; t < 4; ++t) {
                    uint32_t b0 = wrow[t * 8];
                    uint32_t b1 = wrow[t * 8 + 4 * WSTRIDE];
                    asm volatile(
                        "mma.sync.aligned.m16n8k16.row.col.f32.f16.f16.f32 "
                        "{%0,%1,%2,%3}, {%4,%5,%6,%7}, {%8,%9}, {%0,%1,%2,%3};"
                        : "+f"(acc[2*t][0]), "+f"(acc[2*t][1]),
                          "+f"(acc[2*t][2]), "+f"(acc[2*t][3])
                        : "r"(a0), "r"(a1), "r"(a2), "r"(a3), "r"(b0), "r"(b1));
                    asm volatile(
                        "mma.sync.aligned.m16n8k16.row.col.f32.f16.f16.f32 "
                        "{%0,%1,%2,%3}, {%4,%5,%6,%7}, {%8,%9}, {%0,%1,%2,%3};"
                        : "+f"(acc[2*t+1][0]), "+f"(acc[2*t+1][1]),
                          "+f"(acc[2*t+1][2]), "+f"(acc[2*t+1][3])
                        : "r"(a4), "r"(a5), "r"(a6), "r"(a7), "r"(b0), "r"(b1));
                }
            }
            __syncthreads();             // all warps done with slab j before overwrite
            sbuf ^= 1;
        }

        // Prefetch next tile's slab 0 so its latency hides under the epilogue.
        if (tile + step < numTiles) {
            gather_slab((const int*)(sm_ + IDX_OFF + (ibuf ^ 1) * IDX_U32), 0,
                        sb + (A_OFF + sbuf * A_U32) * 4);
            cp_commit();
        }

        // Epilogue: coalesced streaming float2 stores.
        const int rowbase = tile * BLOCK_M;
        #pragma unroll
        for (int s = 0; s < 2; ++s) {
            #pragma unroll
            for (int h = 0; h < 2; ++h) {
                int r = rowbase + mw * 32 + s * 16 + h * 8 + qr;
                if (r < NFINE) {
                    float2* po = (float2*)(out + (size_t)r * NF + nh * 32 + qc * 2);
                    #pragma unroll
                    for (int t = 0; t < 4; ++t)
                        __stcs(po + t * 4,
                               make_float2(acc[2*t + s][2*h], acc[2*t + s][2*h + 1]));
                }
            }
        }
        ibuf ^= 1;
    }
}

extern "C" void kernel_launch(void* const* d_in, const int* in_sizes, int n_in,
                              void* d_out, int out_size)
{
    const float* coarse = (const float*)d_in[0];   // [250000, 32] f32
    const int*   nbr    = (const int*)  d_in[1];   // [1000000, 9] i32
    const float* weight = (const float*)d_in[2];   // [288, 64] f32
    float*       out    = (float*)d_out;           // [1000000, 64] f32

    cudaFuncSetAttribute(finefy_fp16_kernel,
                         cudaFuncAttributeMaxDynamicSharedMemorySize, SMEM_BYTES);

    int nsm = 148;
    cudaDeviceGetAttribute(&nsm, cudaDevAttrMultiProcessorCount, 0);

    // Pre-pass: convert coarse lattice to fp16 (deterministic, graph-capturable).
    conv_coarse<<<nsm * 4, 256>>>((const float4*)coarse);

    const int numTiles = (NFINE + BLOCK_M - 1) / BLOCK_M;   // 3907
    finefy_fp16_kernel<<<nsm, THREADS, SMEM_BYTES>>>(nbr, weight, out, numTiles);
}